// round 15
// baseline (speedup 1.0000x reference)
#include <cuda_runtime.h>
#include <cuda_fp16.h>
#include <cstdint>

// Shapes fixed by the reference: B=4, S=4096, D=1024.
#define BB 4
#define SS 4096
#define DD 1024
#define MQ (BB * SS)     // 16384

// ql/kl/vl hold exp(logit).  Tq/Tk/Tv are RAW sums of exp.
// kvt' = 65536 * sum(ev*ek) / (Tv[i]*Tk[j])  (values ~16, fp16-safe)
// out  = acc * 2^-21 / Tq[m]   (2^-21 = 65536^-1 * 32^-1 ... exact pow2 algebra)
#define OUT_NUM (1.0f / 2097152.0f)       // 2^-21
#define KVT_NUM 65536.0f                  // 2^16

// ---------------------------------------------------------------------------
// Device scratch (allocation-free rule)
// ---------------------------------------------------------------------------
__device__ __half g_hh[(long long)MQ * DD];           // h fp16
__device__ __half g_w3[(long long)3 * DD * DD];       // [Wq;Wk;Wv] fp16
__device__ __half g_ql[(long long)MQ * DD];           // exp(q logits) fp16
__device__ __half g_kl[(long long)MQ * DD];           // exp(k logits) fp16
__device__ __half g_vl[(long long)MQ * DD];           // exp(v logits) fp16
__device__ __half g_kvt[(long long)BB * DD * DD];     // kvt' fp16
__device__ float  g_kvtacc[(long long)BB * DD * DD];  // split-K fp32 accumulator
__device__ float  g_Tq[MQ];                           // rowsum(exp q)
__device__ float  g_Tk[BB * DD];                      // colsum(exp k)
__device__ float  g_Tv[BB * DD];

// ---------------------------------------------------------------------------
// PTX helpers (baseline sm_80+ ISA — safe through compute_100 lowering)
// ---------------------------------------------------------------------------
__device__ __forceinline__ uint32_t smem_u32(const void* p) {
    uint32_t a;
    asm("{ .reg .u64 t; cvta.to.shared.u64 t, %1; cvt.u32.u64 %0, t; }" : "=r"(a) : "l"(p));
    return a;
}
#define CP_ASYNC16(dst, src) \
    asm volatile("cp.async.cg.shared.global [%0], [%1], 16;" :: "r"(dst), "l"(src) : "memory")
#define CP_COMMIT() asm volatile("cp.async.commit_group;" ::: "memory")
#define CP_WAIT1()  asm volatile("cp.async.wait_group 1;" ::: "memory")

__device__ __forceinline__ void ldsm_x4(uint32_t (&r)[4], uint32_t addr) {
    asm volatile("ldmatrix.sync.aligned.m8n8.x4.shared.b16 {%0,%1,%2,%3}, [%4];"
                 : "=r"(r[0]), "=r"(r[1]), "=r"(r[2]), "=r"(r[3]) : "r"(addr));
}
__device__ __forceinline__ void ldsm_x4t(uint32_t (&r)[4], uint32_t addr) {
    asm volatile("ldmatrix.sync.aligned.m8n8.x4.trans.shared.b16 {%0,%1,%2,%3}, [%4];"
                 : "=r"(r[0]), "=r"(r[1]), "=r"(r[2]), "=r"(r[3]) : "r"(addr));
}
__device__ __forceinline__ void mma16816(float* c, const uint32_t* a, uint32_t b0, uint32_t b1) {
    asm volatile("mma.sync.aligned.m16n8k16.row.col.f32.f16.f16.f32 "
                 "{%0,%1,%2,%3}, {%4,%5,%6,%7}, {%8,%9}, {%0,%1,%2,%3};"
                 : "+f"(c[0]), "+f"(c[1]), "+f"(c[2]), "+f"(c[3])
                 : "r"(a[0]), "r"(a[1]), "r"(a[2]), "r"(a[3]), "r"(b0), "r"(b1));
}
// SW64 swizzle for 64-byte rows (BK=32 halves): bits[4:5] ^= bits[7:8].
__device__ __forceinline__ uint32_t swz(uint32_t byte_off) {
    return byte_off ^ ((byte_off >> 3) & 0x30u);
}

struct EpiArgs {
    void* c0; void* c1; void* c2;
    const float* b0; const float* b1; const float* b2;
    float* ra0;          // Tq accumulator (rowsums, global rows)
    float* ra1;          // Tk accumulator (per-batch colsums)
    float* ra2;          // Tv accumulator
    const float* rs;     // raw rowsums Tq (RS path divides by these)
    float oscale;
};
struct W3Args { const float* w0; const float* w1; const float* w2; };

// ---------------------------------------------------------------------------
// fp16 HMMA GEMM: 128x128x32, 3-stage cp.async pipeline, 48KB static, 2 CTA/SM.
//   C[M,N] = A[M,K](K-major,lda) @ B[N,K](K-major,ldb)^T
//   P3: write exp(acc+bias) fp16 routed to q/k/v by n/1024, AND fold in the
//       softmax reductions (rowsums for q, per-batch colsums for k/v).
//   RS: fp32 out scaled by oscale / rs[global row].
// ---------------------------------------------------------------------------
template <bool P3, bool RS>
__global__ void __launch_bounds__(256, 2)
gemm_mma(const __half* __restrict__ A, int lda,
         const __half* __restrict__ B, int ldb,
         EpiArgs ep, int ldc, int K,
         long long sA, long long sB, long long sC)
{
    __shared__ __align__(1024) char smem[3 * 16384];  // per stage: A 8KB + B 8KB

    const int tid = threadIdx.x;
    const int bz  = blockIdx.z;
    const __half* Ab = A + (long long)bz * sA;
    const __half* Bb = B + (long long)bz * sB;

    const int m0 = blockIdx.y * 128;
    const int n0 = blockIdx.x * 128;

    const int wid  = tid >> 5;
    const int lane = tid & 31;
    const int wm   = wid >> 2;
    const int wn   = wid & 3;
    const int fr   = lane & 15;
    const int kc   = lane >> 4;
    const int lr   = tid >> 2;
    const int lc   = tid & 3;

    const uint32_t sm_base = smem_u32(smem);

    auto issue = [&](int kt) {
        const int k0 = kt * 32;
        const int st = kt % 3;
        const uint32_t sa = sm_base + st * 16384;
        const uint32_t sb = sa + 8192;
#pragma unroll
        for (int i = 0; i < 2; i++) {
            const int r = lr + i * 64;
            const uint32_t off = swz((uint32_t)(r * 64 + lc * 16));
            CP_ASYNC16(sa + off, Ab + (size_t)(m0 + r) * lda + k0 + lc * 8);
            CP_ASYNC16(sb + off, Bb + (size_t)(n0 + r) * ldb + k0 + lc * 8);
        }
        CP_COMMIT();
    };

    float acc[4][4][4];
#pragma unroll
    for (int mi = 0; mi < 4; mi++)
#pragma unroll
        for (int nj = 0; nj < 4; nj++)
#pragma unroll
            for (int d = 0; d < 4; d++) acc[mi][nj][d] = 0.f;

    const int KT = K / 32;
    issue(0);
    issue(1);

    for (int kt = 0; kt < KT; ++kt) {
        CP_WAIT1();
        __syncthreads();
        if (kt + 2 < KT) issue(kt + 2);

        const int st = kt % 3;
        const uint32_t sa = sm_base + st * 16384;
        const uint32_t sb = sa + 8192;

#pragma unroll
        for (int ks = 0; ks < 2; ks++) {
            uint32_t af[4][4];
#pragma unroll
            for (int mi = 0; mi < 4; mi++)
                ldsm_x4(af[mi], sa + swz((uint32_t)((wm * 64 + mi * 16 + fr) * 64 + ks * 32 + kc * 16)));
            uint32_t bfr[2][4];
#pragma unroll
            for (int nj2 = 0; nj2 < 2; nj2++)
                ldsm_x4(bfr[nj2], sb + swz((uint32_t)((wn * 32 + nj2 * 16 + fr) * 64 + ks * 32 + kc * 16)));
#pragma unroll
            for (int mi = 0; mi < 4; mi++)
#pragma unroll
                for (int nj = 0; nj < 4; nj++)
                    mma16816(acc[mi][nj], af[mi],
                             bfr[nj >> 1][nj & 1], bfr[nj >> 1][(nj & 1) + 2]);
        }
    }

    const int qr = lane >> 2;
    const int qc = (lane & 3) * 2;

    if (P3) {
        const int oi = n0 >> 10;                 // 0=q, 1=k, 2=v (CTA-uniform)
        __half* Cp      = (oi == 0) ? (__half*)ep.c0 : (oi == 1) ? (__half*)ep.c1 : (__half*)ep.c2;
        const float* bp = (oi == 0) ? ep.b0 : (oi == 1) ? ep.b1 : ep.b2;
        const int nb = n0 & 1023;

        float racc[8];   // q: [mi][half] rowsums
        float cacc[8];   // k/v: [nj][0/1] colsums
#pragma unroll
        for (int i = 0; i < 8; i++) { racc[i] = 0.f; cacc[i] = 0.f; }

#pragma unroll
        for (int mi = 0; mi < 4; mi++) {
            const int gm = m0 + wm * 64 + mi * 16 + qr;
#pragma unroll
            for (int nj = 0; nj < 4; nj++) {
                const int nn = nb + wn * 32 + nj * 8 + qc;
                const float b0 = bp[nn], b1 = bp[nn + 1];
                const float* a4 = acc[mi][nj];
                const float e0 = __expf(a4[0] + b0), e1 = __expf(a4[1] + b1);
                const float e2 = __expf(a4[2] + b0), e3 = __expf(a4[3] + b1);
                *(__half2*)(Cp + (size_t)gm * ldc + nn)       = __floats2half2_rn(e0, e1);
                *(__half2*)(Cp + (size_t)(gm + 8) * ldc + nn) = __floats2half2_rn(e2, e3);
                if (oi == 0) {
                    racc[2 * mi]     += e0 + e1;
                    racc[2 * mi + 1] += e2 + e3;
                } else {
                    cacc[2 * nj]     += e0 + e2;
                    cacc[2 * nj + 1] += e1 + e3;
                }
            }
        }

        if (oi == 0) {
#pragma unroll
            for (int i = 0; i < 8; i++) {
                float v = racc[i];
                v += __shfl_xor_sync(0xffffffffu, v, 1);
                v += __shfl_xor_sync(0xffffffffu, v, 2);
                if ((lane & 3) == 0) {
                    const int gm = m0 + wm * 64 + (i >> 1) * 16 + qr + (i & 1) * 8;
                    atomicAdd(ep.ra0 + gm, v);
                }
            }
        } else {
            float* ca = ((oi == 1) ? ep.ra1 : ep.ra2) + (m0 >> 12) * DD;
#pragma unroll
            for (int i = 0; i < 8; i++) {
                float v = cacc[i];
                v += __shfl_xor_sync(0xffffffffu, v, 4);
                v += __shfl_xor_sync(0xffffffffu, v, 8);
                v += __shfl_xor_sync(0xffffffffu, v, 16);
                if (qr == 0) {
                    const int col = nb + wn * 32 + (i >> 1) * 8 + qc + (i & 1);
                    atomicAdd(ca + col, v);
                }
            }
        }
    } else {
#pragma unroll
        for (int mi = 0; mi < 4; mi++) {
            const int gm = m0 + wm * 64 + mi * 16 + qr;
            float s0 = ep.oscale, s8 = ep.oscale;
            if (RS) {
                s0 = __fdividef(ep.oscale, ep.rs[(long long)bz * (sC / ldc) + gm]);
                s8 = __fdividef(ep.oscale, ep.rs[(long long)bz * (sC / ldc) + gm + 8]);
            }
            float* Cp = (float*)ep.c0 + (long long)bz * sC;
#pragma unroll
            for (int nj = 0; nj < 4; nj++) {
                const int gn = n0 + wn * 32 + nj * 8 + qc;
                const float* a4 = acc[mi][nj];
                *(float2*)(Cp + (size_t)gm * ldc + gn) = make_float2(a4[0] * s0, a4[1] * s0);
                *(float2*)(Cp + (size_t)(gm + 8) * ldc + gn) = make_float2(a4[2] * s8, a4[3] * s8);
            }
        }
    }
}

// ---------------------------------------------------------------------------
// gemm_kvt (split-K=4): acc[i,j] += sum_{s in slice} vl[s,i]*kl[s,j].
// blockIdx.z in [0,16): batch = z&3, slice = z>>2 (1024 rows each).
// Operands read AS STORED ([S,D]); transposed fragments via ldmatrix.x4.trans.
// Epilogue: fp32 atomicAdd into g_kvtacc (scaling applied by kvt_convert).
// ---------------------------------------------------------------------------
__global__ void __launch_bounds__(256, 2)
gemm_kvt(const __half* __restrict__ vl, const __half* __restrict__ kl,
         float* __restrict__ kvtacc)
{
    __shared__ __align__(1024) char smem[3 * 16384];

    const int tid = threadIdx.x;
    const int bz  = blockIdx.z;
    const int batch = bz & 3;
    const int slice = bz >> 2;
    const long long base = (long long)batch * SS * DD + (long long)slice * 1024 * DD;
    const __half* Ab = vl + base;
    const __half* Bb = kl + base;

    const int m0 = blockIdx.y * 128;
    const int n0 = blockIdx.x * 128;

    const int wid  = tid >> 5;
    const int lane = tid & 31;
    const int wm   = wid >> 2;
    const int wn   = wid & 3;
    const int krow_b = (lane & 7) + ((lane >> 4) << 3);
    const int mhalf  = (lane >> 3) & 1;

    const int grow = tid >> 3;
    const int gch  = tid & 7;

    const uint32_t sm_base = smem_u32(smem);

    auto issue = [&](int kt) {
        const int k0 = kt * 32;
        const int st = kt % 3;
        const uint32_t sa = sm_base + st * 16384;
        const uint32_t sb = sa + 8192;
        const size_t gr = (size_t)(k0 + grow) * DD;
#pragma unroll
        for (int i = 0; i < 2; i++) {
            const int cc = gch + i * 8;
            const uint32_t off = (uint32_t)(grow * 256 + (((cc) ^ (grow & 7)) << 4));
            CP_ASYNC16(sa + off, Ab + gr + m0 + cc * 8);
            CP_ASYNC16(sb + off, Bb + gr + n0 + cc * 8);
        }
        CP_COMMIT();
    };

    float acc[4][4][4];
#pragma unroll
    for (int mi = 0; mi < 4; mi++)
#pragma unroll
        for (int nj = 0; nj < 4; nj++)
#pragma unroll
            for (int d = 0; d < 4; d++) acc[mi][nj][d] = 0.f;

    const int KT = 1024 / 32;   // 32 per slice
    issue(0);
    issue(1);

    for (int kt = 0; kt < KT; ++kt) {
        CP_WAIT1();
        __syncthreads();
        if (kt + 2 < KT) issue(kt + 2);

        const int st = kt % 3;
        const uint32_t sa = sm_base + st * 16384;
        const uint32_t sb = sa + 8192;

#pragma unroll
        for (int ks = 0; ks < 2; ks++) {
            const int krow = ks * 16 + krow_b;
            const int kx   = krow & 7;
            uint32_t af[4][4];
#pragma unroll
            for (int mi = 0; mi < 4; mi++) {
                const int chunk = ((wm * 64 + mi * 16) >> 3) + mhalf;
                ldsm_x4t(af[mi], sa + (uint32_t)(krow * 256 + ((chunk ^ kx) << 4)));
            }
            uint32_t bfr[2][4];
#pragma unroll
            for (int nj2 = 0; nj2 < 2; nj2++) {
                const int chunk = ((wn * 32 + nj2 * 16) >> 3) + mhalf;
                ldsm_x4t(bfr[nj2], sb + (uint32_t)(krow * 256 + ((chunk ^ kx) << 4)));
            }
#pragma unroll
            for (int mi = 0; mi < 4; mi++)
#pragma unroll
                for (int nj = 0; nj < 4; nj++)
                    mma16816(acc[mi][nj], af[mi],
                             bfr[nj >> 1][nj & 1], bfr[nj >> 1][(nj & 1) + 2]);
        }
    }

    const int qr = lane >> 2;
    const int qc = (lane & 3) * 2;
    float* Cb = kvtacc + (long long)batch * DD * DD;

#pragma unroll
    for (int mi = 0; mi < 4; mi++) {
        const int gm = m0 + wm * 64 + mi * 16 + qr;
#pragma unroll
        for (int nj = 0; nj < 4; nj++) {
            const int gn = n0 + wn * 32 + nj * 8 + qc;
            const float* a4 = acc[mi][nj];
            atomicAdd(Cb + (size_t)gm * DD + gn,       a4[0]);
            atomicAdd(Cb + (size_t)gm * DD + gn + 1,   a4[1]);
            atomicAdd(Cb + (size_t)(gm + 8) * DD + gn,     a4[2]);
            atomicAdd(Cb + (size_t)(gm + 8) * DD + gn + 1, a4[3]);
        }
    }
}

// ---------------------------------------------------------------------------
// kvt_convert: kvt_f16[b,i,j] = 65536 * acc[b,i,j] / (Tv[b,i] * Tk[b,j]).
// One thread = 4 consecutive j of one row. grid BB*DD*DD/1024, block 256.
// ---------------------------------------------------------------------------
__global__ void kvt_convert(const float* __restrict__ acc,
                            const float* __restrict__ Tv,
                            const float* __restrict__ Tk,
                            __half* __restrict__ kvt)
{
    const size_t idx = ((size_t)blockIdx.x * 256 + threadIdx.x) * 4;
    const int b = (int)(idx >> 20);
    const size_t rem = idx & 1048575;
    const int i = (int)(rem >> 10);
    const int j = (int)(rem & 1023);

    float4 a  = *(const float4*)(acc + idx);
    float4 tk = *(const float4*)(Tk + b * DD + j);
    const float rv = __fdividef(KVT_NUM, Tv[b * DD + i]);

    __half2 o0 = __floats2half2_rn(__fdividef(a.x * rv, tk.x),
                                   __fdividef(a.y * rv, tk.y));
    __half2 o1 = __floats2half2_rn(__fdividef(a.z * rv, tk.z),
                                   __fdividef(a.w * rv, tk.w));
    *(__half2*)(kvt + idx)     = o0;
    *(__half2*)(kvt + idx + 2) = o1;
}

// ---------------------------------------------------------------------------
// Fused conversion: h fp32 -> fp16 AND [Wq;Wk;Wv] fp32 -> fp16, one launch.
// ---------------------------------------------------------------------------
__global__ void conv_all_kernel(const float* __restrict__ h, W3Args w,
                                __half* __restrict__ hh, __half* __restrict__ w3)
{
    const size_t idx = ((size_t)blockIdx.x * 256 + threadIdx.x) * 4;
    const float* src;
    __half* dst;
    if (idx < (size_t)MQ * DD) {
        src = h + idx;
        dst = hh + idx;
    } else {
        const size_t i2  = idx - (size_t)MQ * DD;
        const int    oi  = (int)(i2 >> 20);
        const size_t rem = i2 & 1048575;
        src = ((oi == 0) ? w.w0 : (oi == 1) ? w.w1 : w.w2) + rem;
        dst = w3 + (size_t)oi * 1048576 + rem;
    }
    float4 x = *(const float4*)src;
    __half o[4] = { __float2half_rn(x.x), __float2half_rn(x.y),
                    __float2half_rn(x.z), __float2half_rn(x.w) };
    *(uint2*)dst = *(const uint2*)o;
}

// ---------------------------------------------------------------------------
// launch
// ---------------------------------------------------------------------------
extern "C" void kernel_launch(void* const* d_in, const int* in_sizes, int n_in,
                              void* d_out, int out_size)
{
    const float* h  = (const float*)d_in[0];
    const float* Wq = (const float*)d_in[1];
    const float* bq = (const float*)d_in[2];
    const float* Wk = (const float*)d_in[3];
    const float* bk = (const float*)d_in[4];
    const float* Wv = (const float*)d_in[5];
    const float* bv = (const float*)d_in[6];
    float* out = (float*)d_out;

    __half *hh, *w3, *ql, *kl, *vl, *kvt;
    float *kvtacc, *Tq, *Tk, *Tv;
    cudaGetSymbolAddress((void**)&hh,     g_hh);
    cudaGetSymbolAddress((void**)&w3,     g_w3);
    cudaGetSymbolAddress((void**)&ql,     g_ql);
    cudaGetSymbolAddress((void**)&kl,     g_kl);
    cudaGetSymbolAddress((void**)&vl,     g_vl);
    cudaGetSymbolAddress((void**)&kvt,    g_kvt);
    cudaGetSymbolAddress((void**)&kvtacc, g_kvtacc);
    cudaGetSymbolAddress((void**)&Tq,     g_Tq);
    cudaGetSymbolAddress((void**)&Tk,     g_Tk);
    cudaGetSymbolAddress((void**)&Tv,     g_Tv);

    // 0) zero the accumulators (stream memset nodes; capture-legal)
    cudaMemsetAsync(Tq, 0, MQ * sizeof(float));
    cudaMemsetAsync(Tk, 0, BB * DD * sizeof(float));
    cudaMemsetAsync(Tv, 0, BB * DD * sizeof(float));
    cudaMemsetAsync(kvtacc, 0, (size_t)BB * DD * DD * sizeof(float));

    // 1) fp16 conversions (h + all three weights, one launch)
    {
        W3Args wa{ Wq, Wk, Wv };
        const int total = (MQ * DD + 3 * DD * DD) / 1024;
        conv_all_kernel<<<total, 256>>>(h, wa, hh, w3);
    }

    // 2) fused projection GEMM -> exp(logit+bias) fp16 for q/k/v, with the
    //    softmax reductions folded into the epilogue (atomics into Tq/Tk/Tv).
    {
        EpiArgs ep{ ql, kl, vl, bq, bk, bv, Tq, Tk, Tv, nullptr, 1.0f };
        gemm_mma<true, false><<<dim3(24, 128, 1), 256>>>(
            hh, DD, w3, DD, ep, DD, DD, 0, 0, 0);
    }

    // 3) kvt split-K=4: 1024 CTAs (load-balanced), fp32 atomic accumulation
    gemm_kvt<<<dim3(8, 8, 16), 256>>>(vl, kl, kvtacc);

    // 4) scale + convert: kvt' = 65536*acc/(Tv[i]*Tk[j]) in fp16
    kvt_convert<<<BB * DD * DD / 1024, 256>>>(kvtacc, Tv, Tk, kvt);

    // 5) out[m,n] = (2^-21 / Tq[m]) * sum_a ql[m,a] * kvt'[n,a]
    {
        EpiArgs ep{ out, nullptr, nullptr, nullptr, nullptr, nullptr,
                    nullptr, nullptr, nullptr, Tq, OUT_NUM };
        gemm_mma<false, true><<<dim3(8, 32, BB), 256>>>(
            ql, DD, kvt, DD, ep, DD, DD,
            (long long)SS * DD, (long long)DD * DD, (long long)SS * DD);
    }
}